// round 12
// baseline (speedup 1.0000x reference)
#include <cuda_runtime.h>
#include <math.h>

#define NB 16384
#define NIN 128
#define NH 512
#define NY 32
#define NK 8

static __device__ float g_feat[NB * NH];     // 32 MB scratch
static __device__ float g_D[NB * NY];        // 2 MB  (D = softplus+1e-3)
static __device__ float g_V[NB * NY * NK];   // 16 MB

typedef unsigned long long ull;

__device__ __forceinline__ ull pack2(float lo, float hi) {
    ull r; asm("mov.b64 %0, {%1, %2};" : "=l"(r) : "f"(lo), "f"(hi)); return r;
}
__device__ __forceinline__ void unpack2(ull v, float& lo, float& hi) {
    asm("mov.b64 {%0, %1}, %2;" : "=f"(lo), "=f"(hi) : "l"(v));
}
__device__ __forceinline__ ull fma2_(ull a, ull b, ull c) {
    ull d; asm("fma.rn.f32x2 %0, %1, %2, %3;" : "=l"(d) : "l"(a), "l"(b), "l"(c)); return d;
}
__device__ __forceinline__ ull mul2_(ull a, ull b) {
    ull d; asm("mul.rn.f32x2 %0, %1, %2;" : "=l"(d) : "l"(a), "l"(b)); return d;
}

__device__ __forceinline__ float softplus_f(float v) {
    return (v > 20.f) ? v : log1pf(expf(v));
}

// ---------------------------------------------------------------------------
// K1: feat = relu(x @ W1 + b1)   [16384,128] @ [128,512]   (validated)
// ---------------------------------------------------------------------------
__global__ void __launch_bounds__(256) feat_kernel(const float* __restrict__ x,
                                                   const float* __restrict__ W1,
                                                   const float* __restrict__ b1) {
    __shared__ float Xs[32][68];
    __shared__ float Ws[32][68];
    const int bm = blockIdx.y * 64;
    const int bn = blockIdx.x * 64;
    const int tid = threadIdx.x;
    const int tx = tid & 15, ty = tid >> 4;

    float acc[4][4];
#pragma unroll
    for (int i = 0; i < 4; i++)
#pragma unroll
        for (int jj = 0; jj < 4; jj++) acc[i][jj] = 0.f;

    for (int k0 = 0; k0 < NIN; k0 += 32) {
#pragma unroll
        for (int t = 0; t < 8; t++) {
            int idx = tid + t * 256;
            int m = idx >> 5, k = idx & 31;
            Xs[k][m] = x[(size_t)(bm + m) * NIN + k0 + k];
        }
#pragma unroll
        for (int t = 0; t < 8; t++) {
            int idx = tid + t * 256;
            int k = idx >> 6, n = idx & 63;
            Ws[k][n] = W1[(size_t)(k0 + k) * NH + bn + n];
        }
        __syncthreads();
#pragma unroll
        for (int k = 0; k < 32; k++) {
            float4 a  = *(const float4*)&Xs[k][ty * 4];
            float4 bq = *(const float4*)&Ws[k][tx * 4];
            float av[4] = {a.x, a.y, a.z, a.w};
            float bv[4] = {bq.x, bq.y, bq.z, bq.w};
#pragma unroll
            for (int i = 0; i < 4; i++)
#pragma unroll
                for (int jj = 0; jj < 4; jj++)
                    acc[i][jj] = fmaf(av[i], bv[jj], acc[i][jj]);
        }
        __syncthreads();
    }
#pragma unroll
    for (int i = 0; i < 4; i++) {
        int m = bm + ty * 4 + i;
#pragma unroll
        for (int jj = 0; jj < 4; jj++) {
            int n = bn + tx * 4 + jj;
            float v = acc[i][jj] + b1[n];
            g_feat[(size_t)m * NH + n] = fmaxf(v, 0.f);
        }
    }
}

// ---------------------------------------------------------------------------
// K2: head GEMM. mode 0: D = softplus(feat@WD+bD)+1e-3  (N=32)
//                mode 1: V = feat@WV+bV                 (N=256)   (validated)
// ---------------------------------------------------------------------------
__global__ void __launch_bounds__(256) head_kernel(const float* __restrict__ Wmat,
                                                   const float* __restrict__ bias,
                                                   int N, int mode) {
    __shared__ float Fs[32][132];
    __shared__ float Ws2[32][36];
    const int bm = blockIdx.y * 128;
    const int bn = blockIdx.x * 32;
    const int tid = threadIdx.x;
    const int tx = tid & 7, ty = tid >> 3;

    float acc[4][4];
#pragma unroll
    for (int i = 0; i < 4; i++)
#pragma unroll
        for (int jj = 0; jj < 4; jj++) acc[i][jj] = 0.f;

    for (int k0 = 0; k0 < NH; k0 += 32) {
#pragma unroll
        for (int t = 0; t < 16; t++) {
            int idx = tid + t * 256;
            int m = idx >> 5, k = idx & 31;
            Fs[k][m] = g_feat[(size_t)(bm + m) * NH + k0 + k];
        }
#pragma unroll
        for (int t = 0; t < 4; t++) {
            int idx = tid + t * 256;
            int k = idx >> 5, n = idx & 31;
            Ws2[k][n] = Wmat[(size_t)(k0 + k) * N + bn + n];
        }
        __syncthreads();
#pragma unroll
        for (int k = 0; k < 32; k++) {
            float4 a  = *(const float4*)&Fs[k][ty * 4];
            float4 bq = *(const float4*)&Ws2[k][tx * 4];
            float av[4] = {a.x, a.y, a.z, a.w};
            float bv[4] = {bq.x, bq.y, bq.z, bq.w};
#pragma unroll
            for (int i = 0; i < 4; i++)
#pragma unroll
                for (int jj = 0; jj < 4; jj++)
                    acc[i][jj] = fmaf(av[i], bv[jj], acc[i][jj]);
        }
        __syncthreads();
    }
#pragma unroll
    for (int i = 0; i < 4; i++) {
        int m = bm + ty * 4 + i;
#pragma unroll
        for (int jj = 0; jj < 4; jj++) {
            int n = bn + tx * 4 + jj;
            float v = acc[i][jj] + bias[n];
            if (mode == 0) {
                g_D[(size_t)m * NY + n] = softplus_f(v) + 1e-3f;
            } else {
                g_V[(size_t)m * (NY * NK) + n] = v;
            }
        }
    }
}

// ---------------------------------------------------------------------------
// K3: Givens-QR compresses G = [diag(D); V^T] (40x32) to upper-triangular
// R (32x32), then one-sided Jacobi on 32-length register columns.
// (128,7): 28 warps/SM (reg cap 73; hot loop needs ~72).
// ---------------------------------------------------------------------------
__global__ void __launch_bounds__(128, 7) jacobi_kernel(float* __restrict__ out) {
    __shared__ float Bsh[4][32][33];   // R -> W (eigvecs) -> output rows
    __shared__ float Gsh[4][32][33];   // converged g' columns
    __shared__ float phsh[4][32];

    const int w = threadIdx.x >> 5;
    const int j = threadIdx.x & 31;
    const int b = blockIdx.x * 4 + w;
    const unsigned FULL = 0xffffffffu;

    // ---- load column j of G: top = D_j e_j, bottom = V[j][:] -------------
    const float Dj = g_D[(size_t)b * NY + j];
    const float4 v0 = *(const float4*)&g_V[(size_t)b * 256 + j * 8];
    const float4 v1 = *(const float4*)&g_V[(size_t)b * 256 + j * 8 + 4];

    float tf[32];
#pragma unroll
    for (int i = 0; i < 32; i++) tf[i] = (i == j) ? Dj : 0.f;
    float bt[8] = {v0.x, v0.y, v0.z, v0.w, v1.x, v1.y, v1.z, v1.w};

    // ---- Givens QR: zero the 8 bottom rows --------------------------------
#pragma unroll
    for (int jj = 0; jj < 32; jj++) {
#pragma unroll
        for (int k = 0; k < 8; k++) {
            float a, bb;
            { ull ab = __shfl_sync(FULL, pack2(tf[jj], bt[k]), jj);
              unpack2(ab, a, bb); }
            // pivot a = R[jj][jj] >= D_jj >= 1e-3 > 0 always
            float rinv = rsqrtf(fmaf(a, a, bb * bb));
            float c = a * rinv, s = bb * rinv;
            float t1 = fmaf(c, tf[jj], s * bt[k]);
            bt[k]  = fmaf(c, bt[k], -s * tf[jj]);
            tf[jj] = t1;
        }
    }

    // ---- stage R to smem (column j), compute column norm ------------------
    float nrm = 0.f;
#pragma unroll
    for (int i = 0; i < 32; i++) {
        Bsh[w][i][j] = tf[i];
        nrm = fmaf(tf[i], tf[i], nrm);
    }
    __syncwarp();

    // ---- pack into 16 f32x2 registers -------------------------------------
    ull gp[16];
#pragma unroll
    for (int i = 0; i < 16; i++) gp[i] = pack2(tf[2 * i], tf[2 * i + 1]);

    float e = 1.f;                              // column scale^2 (d^2)
    const float tol2 = 1e-11f;                  // (~3e-6)^2 relative (validated)

    // ---- one-sided Jacobi sweeps (XOR tournament: m = 1..31) -------------
    for (int sweep = 0; sweep < 12; sweep++) {
        int did = 0;
        for (int m = 1; m < 32; m++) {
            // fetch partner column ONCE (reused for dot + update)
            ull hp[16];
#pragma unroll
            for (int i = 0; i < 16; i++)
                hp[i] = __shfl_xor_sync(FULL, gp[i], m);
            float nrmo, eo;
            { ull neo = __shfl_xor_sync(FULL, pack2(nrm, e), m);
              unpack2(neo, nrmo, eo); }

            // dot: a_pq(stored), 4 accumulators (bitwise-identical on pair)
            ull a0 = 0ull, a1 = 0ull, a2v = 0ull, a3 = 0ull;
#pragma unroll
            for (int i = 0; i < 16; i += 4) {
                a0  = fma2_(gp[i],     hp[i],     a0);
                a1  = fma2_(gp[i + 1], hp[i + 1], a1);
                a2v = fma2_(gp[i + 2], hp[i + 2], a2v);
                a3  = fma2_(gp[i + 3], hp[i + 3], a3);
            }
            float f0l, f0h, f1l, f1h, f2l, f2h, f3l, f3h;
            unpack2(a0, f0l, f0h);  unpack2(a1, f1l, f1h);
            unpack2(a2v, f2l, f2h); unpack2(a3, f3l, f3h);
            float apq = ((f0l + f0h) + (f1l + f1h)) + ((f2l + f2h) + (f3l + f3h));

            // scale-invariant threshold
            bool rot = apq * apq > tol2 * nrm * nrmo;
            if (__any_sync(FULL, rot)) {
                did = 1;
                bool isp = j < (j ^ m);
                // tau = (aqq - app)_true / (2*apq_true); same on both lanes
                float dn = isp ? (eo * nrmo - e * nrm) : (e * nrm - eo * nrmo);
                float inv_sd = rsqrtf(e * eo);         // 1/sqrt(e*eo)
                float tau = __fdividef(dn * (0.5f * inv_sd), apq);
                float t = copysignf(1.f, tau) / (fabsf(tau) + sqrtf(fmaf(tau, tau, 1.f)));
                if (!rot) t = 0.f;
                float rr = eo * inv_sd;                // sqrt(eo/e)
                float al = (isp ? -t : t) * rr;        // g += al * h
                ull a2p = pack2(al, al);
#pragma unroll
                for (int i = 0; i < 16; i++)
                    gp[i] = fma2_(a2p, hp[i], gp[i]);
                float ct2 = fmaf(t, t, 1.f);           // 1/c^2
                nrm = fmaf(al, apq, nrm) * ct2;        // stored-norm update
                e = __fdividef(e, ct2);                // d'^2 = c^2 d^2
            }
        }
        // ---- fold scale back into the column; exact norm recompute -------
        float d = sqrtf(e);
        ull d2 = pack2(d, d);
        ull na0 = 0ull, na1 = 0ull;
#pragma unroll
        for (int i = 0; i < 16; i += 2) {
            gp[i]     = mul2_(gp[i],     d2);
            gp[i + 1] = mul2_(gp[i + 1], d2);
            na0 = fma2_(gp[i],     gp[i],     na0);
            na1 = fma2_(gp[i + 1], gp[i + 1], na1);
        }
        float nlo, nhi, mlo, mhi;
        unpack2(na0, nlo, nhi); unpack2(na1, mlo, mhi);
        nrm = (nlo + mlo) + (nhi + mhi);
        e = 1.f;
        if (!did) break;
    }

    // ---- epilogue: eigenvalue + eigenvector recovery ---------------------
    float gf[32];
#pragma unroll
    for (int i = 0; i < 16; i++) unpack2(gp[i], gf[2 * i], gf[2 * i + 1]);

    const float s2 = nrm;                        // ||g'||^2 (exact from fold)
    const float fj = sqrtf(__fdividef(1.f, s2) + 1e-6f);  // sqrt(lam + EPS)

    // stage g' column to smem (needed for dynamic-index recovery loop)
#pragma unroll
    for (int i = 0; i < 32; i++) Gsh[w][i][j] = gf[i];
    __syncwarp();

    // w = R^T g'; accw[i] = sum_m R[m][i] * g'_m
    float accw[32];
#pragma unroll
    for (int i = 0; i < 32; i++) accw[i] = 0.f;
    for (int m = 0; m < 32; m++) {
        float gm = Gsh[w][m][j];                 // own column, conflict-free
#pragma unroll
        for (int i = 0; i < 32; i++)
            accw[i] = fmaf(Bsh[w][m][i], gm, accw[i]);   // broadcast loads
    }
    float nn = 0.f;
#pragma unroll
    for (int i = 0; i < 32; i++) nn = fmaf(accw[i], accw[i], nn);
    phsh[w][j] = __fdividef(fj, nn);             // phi = f / ||w||^2
    __syncwarp();

    // overwrite Bsh with W (unscaled eigvec columns)
#pragma unroll
    for (int i = 0; i < 32; i++) Bsh[w][i][j] = accw[i];
    __syncwarp();

    // ---- out = sum_k phi_k * w_k w_k^T  (row j per lane) -----------------
    float accO[32];
#pragma unroll
    for (int i = 0; i < 32; i++) accO[i] = 0.f;
    for (int k = 0; k < 32; k++) {
        float qjk = Bsh[w][j][k] * phsh[w][k];   // stride-33: conflict-free
#pragma unroll
        for (int i = 0; i < 32; i++)
            accO[i] = fmaf(Bsh[w][i][k], qjk, accO[i]);  // broadcast loads
    }
    __syncwarp();
#pragma unroll
    for (int i = 0; i < 32; i++) Bsh[w][j][i] = accO[i];  // stage row j
    __syncwarp();

    float* ob = out + (size_t)b * 1024;
#pragma unroll
    for (int t = 0; t < 8; t++) {                // coalesced 512B stores
        int idx = t * 128 + j * 4;
        int rr = idx >> 5, cc = idx & 31;
        float4 val = make_float4(Bsh[w][rr][cc], Bsh[w][rr][cc + 1],
                                 Bsh[w][rr][cc + 2], Bsh[w][rr][cc + 3]);
        *(float4*)&ob[idx] = val;
    }
}

// ---------------------------------------------------------------------------
extern "C" void kernel_launch(void* const* d_in, const int* in_sizes, int n_in,
                              void* d_out, int out_size) {
    const float* x  = (const float*)d_in[0];
    const float* W1 = (const float*)d_in[1];
    const float* b1 = (const float*)d_in[2];
    const float* WD = (const float*)d_in[3];
    const float* bD = (const float*)d_in[4];
    const float* WV = (const float*)d_in[5];
    const float* bV = (const float*)d_in[6];
    float* out = (float*)d_out;

    dim3 g1(NH / 64, NB / 64);
    feat_kernel<<<g1, 256>>>(x, W1, b1);

    dim3 g2a(1, NB / 128);
    head_kernel<<<g2a, 256>>>(WD, bD, 32, 0);

    dim3 g2b((NY * NK) / 32, NB / 128);
    head_kernel<<<g2b, 256>>>(WV, bV, 256, 1);

    jacobi_kernel<<<NB / 4, 128>>>(out);
}

// round 14
// speedup vs baseline: 1.3737x; 1.3737x over previous
#include <cuda_runtime.h>
#include <math.h>

#define NB 16384
#define NIN 128
#define NH 512
#define NY 32
#define NK 8

static __device__ float g_feat[NB * NH];     // 32 MB scratch
static __device__ float g_D[NB * NY];        // 2 MB  (D = softplus+1e-3)
static __device__ float g_V[NB * NY * NK];   // 16 MB

typedef unsigned long long ull;

__device__ __forceinline__ ull pack2(float lo, float hi) {
    ull r; asm("mov.b64 %0, {%1, %2};" : "=l"(r) : "f"(lo), "f"(hi)); return r;
}
__device__ __forceinline__ void unpack2(ull v, float& lo, float& hi) {
    asm("mov.b64 {%0, %1}, %2;" : "=f"(lo), "=f"(hi) : "l"(v));
}
__device__ __forceinline__ ull fma2_(ull a, ull b, ull c) {
    ull d; asm("fma.rn.f32x2 %0, %1, %2, %3;" : "=l"(d) : "l"(a), "l"(b), "l"(c)); return d;
}
__device__ __forceinline__ ull mul2_(ull a, ull b) {
    ull d; asm("mul.rn.f32x2 %0, %1, %2;" : "=l"(d) : "l"(a), "l"(b)); return d;
}

__device__ __forceinline__ float softplus_f(float v) {
    return (v > 20.f) ? v : log1pf(expf(v));
}

// ---------------------------------------------------------------------------
// K1: feat = relu(x @ W1 + b1)   [16384,128] @ [128,512]   (validated)
// ---------------------------------------------------------------------------
__global__ void __launch_bounds__(256) feat_kernel(const float* __restrict__ x,
                                                   const float* __restrict__ W1,
                                                   const float* __restrict__ b1) {
    __shared__ float Xs[32][68];
    __shared__ float Ws[32][68];
    const int bm = blockIdx.y * 64;
    const int bn = blockIdx.x * 64;
    const int tid = threadIdx.x;
    const int tx = tid & 15, ty = tid >> 4;

    float acc[4][4];
#pragma unroll
    for (int i = 0; i < 4; i++)
#pragma unroll
        for (int jj = 0; jj < 4; jj++) acc[i][jj] = 0.f;

    for (int k0 = 0; k0 < NIN; k0 += 32) {
#pragma unroll
        for (int t = 0; t < 8; t++) {
            int idx = tid + t * 256;
            int m = idx >> 5, k = idx & 31;
            Xs[k][m] = x[(size_t)(bm + m) * NIN + k0 + k];
        }
#pragma unroll
        for (int t = 0; t < 8; t++) {
            int idx = tid + t * 256;
            int k = idx >> 6, n = idx & 63;
            Ws[k][n] = W1[(size_t)(k0 + k) * NH + bn + n];
        }
        __syncthreads();
#pragma unroll
        for (int k = 0; k < 32; k++) {
            float4 a  = *(const float4*)&Xs[k][ty * 4];
            float4 bq = *(const float4*)&Ws[k][tx * 4];
            float av[4] = {a.x, a.y, a.z, a.w};
            float bv[4] = {bq.x, bq.y, bq.z, bq.w};
#pragma unroll
            for (int i = 0; i < 4; i++)
#pragma unroll
                for (int jj = 0; jj < 4; jj++)
                    acc[i][jj] = fmaf(av[i], bv[jj], acc[i][jj]);
        }
        __syncthreads();
    }
#pragma unroll
    for (int i = 0; i < 4; i++) {
        int m = bm + ty * 4 + i;
#pragma unroll
        for (int jj = 0; jj < 4; jj++) {
            int n = bn + tx * 4 + jj;
            float v = acc[i][jj] + b1[n];
            g_feat[(size_t)m * NH + n] = fmaxf(v, 0.f);
        }
    }
}

// ---------------------------------------------------------------------------
// K2: head GEMM. mode 0: D = softplus(feat@WD+bD)+1e-3  (N=32)
//                mode 1: V = feat@WV+bV                 (N=256)   (validated)
// ---------------------------------------------------------------------------
__global__ void __launch_bounds__(256) head_kernel(const float* __restrict__ Wmat,
                                                   const float* __restrict__ bias,
                                                   int N, int mode) {
    __shared__ float Fs[32][132];
    __shared__ float Ws2[32][36];
    const int bm = blockIdx.y * 128;
    const int bn = blockIdx.x * 32;
    const int tid = threadIdx.x;
    const int tx = tid & 7, ty = tid >> 3;

    float acc[4][4];
#pragma unroll
    for (int i = 0; i < 4; i++)
#pragma unroll
        for (int jj = 0; jj < 4; jj++) acc[i][jj] = 0.f;

    for (int k0 = 0; k0 < NH; k0 += 32) {
#pragma unroll
        for (int t = 0; t < 16; t++) {
            int idx = tid + t * 256;
            int m = idx >> 5, k = idx & 31;
            Fs[k][m] = g_feat[(size_t)(bm + m) * NH + k0 + k];
        }
#pragma unroll
        for (int t = 0; t < 4; t++) {
            int idx = tid + t * 256;
            int k = idx >> 5, n = idx & 31;
            Ws2[k][n] = Wmat[(size_t)(k0 + k) * N + bn + n];
        }
        __syncthreads();
#pragma unroll
        for (int k = 0; k < 32; k++) {
            float4 a  = *(const float4*)&Fs[k][ty * 4];
            float4 bq = *(const float4*)&Ws2[k][tx * 4];
            float av[4] = {a.x, a.y, a.z, a.w};
            float bv[4] = {bq.x, bq.y, bq.z, bq.w};
#pragma unroll
            for (int i = 0; i < 4; i++)
#pragma unroll
                for (int jj = 0; jj < 4; jj++)
                    acc[i][jj] = fmaf(av[i], bv[jj], acc[i][jj]);
        }
        __syncthreads();
    }
#pragma unroll
    for (int i = 0; i < 4; i++) {
        int m = bm + ty * 4 + i;
#pragma unroll
        for (int jj = 0; jj < 4; jj++) {
            int n = bn + tx * 4 + jj;
            float v = acc[i][jj] + bias[n];
            if (mode == 0) {
                g_D[(size_t)m * NY + n] = softplus_f(v) + 1e-3f;
            } else {
                g_V[(size_t)m * (NY * NK) + n] = v;
            }
        }
    }
}

// ---------------------------------------------------------------------------
// K3: Givens-QR compresses G = [diag(D); V^T] (40x32) to upper-triangular
// R (32x32), then one-sided Jacobi on 32-length register columns.
// (128,6): 24 warps/SM, NO reg cap below the hot-loop requirement (~80 natural,
// cap 85) -> no spills.  (128,7) proven harmful in R11 (hot-loop spills).
// ---------------------------------------------------------------------------
__global__ void __launch_bounds__(128, 6) jacobi_kernel(float* __restrict__ out) {
    __shared__ float Bsh[4][32][33];   // R -> W (eigvecs) -> output rows
    __shared__ float Gsh[4][32][33];   // converged g' columns
    __shared__ float phsh[4][32];

    const int w = threadIdx.x >> 5;
    const int j = threadIdx.x & 31;
    const int b = blockIdx.x * 4 + w;
    const unsigned FULL = 0xffffffffu;

    // ---- load column j of G: top = D_j e_j, bottom = V[j][:] -------------
    const float Dj = g_D[(size_t)b * NY + j];
    const float4 v0 = *(const float4*)&g_V[(size_t)b * 256 + j * 8];
    const float4 v1 = *(const float4*)&g_V[(size_t)b * 256 + j * 8 + 4];

    float tf[32];
#pragma unroll
    for (int i = 0; i < 32; i++) tf[i] = (i == j) ? Dj : 0.f;
    float bt[8] = {v0.x, v0.y, v0.z, v0.w, v1.x, v1.y, v1.z, v1.w};

    // ---- Givens QR: zero the 8 bottom rows --------------------------------
#pragma unroll
    for (int jj = 0; jj < 32; jj++) {
#pragma unroll
        for (int k = 0; k < 8; k++) {
            float a, bb;
            { ull ab = __shfl_sync(FULL, pack2(tf[jj], bt[k]), jj);
              unpack2(ab, a, bb); }
            // pivot a = R[jj][jj] >= D_jj >= 1e-3 > 0 always
            float rinv = rsqrtf(fmaf(a, a, bb * bb));
            float c = a * rinv, s = bb * rinv;
            float t1 = fmaf(c, tf[jj], s * bt[k]);
            bt[k]  = fmaf(c, bt[k], -s * tf[jj]);
            tf[jj] = t1;
        }
    }

    // ---- stage R to smem (column j), compute column norm ------------------
    float nrm = 0.f;
#pragma unroll
    for (int i = 0; i < 32; i++) {
        Bsh[w][i][j] = tf[i];
        nrm = fmaf(tf[i], tf[i], nrm);
    }
    __syncwarp();

    // ---- pack into 16 f32x2 registers -------------------------------------
    ull gp[16];
#pragma unroll
    for (int i = 0; i < 16; i++) gp[i] = pack2(tf[2 * i], tf[2 * i + 1]);

    float e = 1.f;                              // column scale^2 (d^2)
    const float tol2 = 1e-11f;                  // (~3e-6)^2 relative (validated)

    // ---- one-sided Jacobi sweeps (XOR tournament: m = 1..31) -------------
    for (int sweep = 0; sweep < 12; sweep++) {
        int did = 0;
        for (int m = 1; m < 32; m++) {
            // fetch partner column ONCE (reused for dot + update)
            ull hp[16];
#pragma unroll
            for (int i = 0; i < 16; i++)
                hp[i] = __shfl_xor_sync(FULL, gp[i], m);
            float nrmo, eo;
            { ull neo = __shfl_xor_sync(FULL, pack2(nrm, e), m);
              unpack2(neo, nrmo, eo); }

            // dot: a_pq(stored), 4 accumulators (bitwise-identical on pair)
            ull a0 = 0ull, a1 = 0ull, a2v = 0ull, a3 = 0ull;
#pragma unroll
            for (int i = 0; i < 16; i += 4) {
                a0  = fma2_(gp[i],     hp[i],     a0);
                a1  = fma2_(gp[i + 1], hp[i + 1], a1);
                a2v = fma2_(gp[i + 2], hp[i + 2], a2v);
                a3  = fma2_(gp[i + 3], hp[i + 3], a3);
            }
            float f0l, f0h, f1l, f1h, f2l, f2h, f3l, f3h;
            unpack2(a0, f0l, f0h);  unpack2(a1, f1l, f1h);
            unpack2(a2v, f2l, f2h); unpack2(a3, f3l, f3h);
            float apq = ((f0l + f0h) + (f1l + f1h)) + ((f2l + f2h) + (f3l + f3h));

            // scale-invariant threshold
            bool rot = apq * apq > tol2 * nrm * nrmo;
            if (__any_sync(FULL, rot)) {
                did = 1;
                bool isp = j < (j ^ m);
                // tau = (aqq - app)_true / (2*apq_true); same on both lanes
                float dn = isp ? (eo * nrmo - e * nrm) : (e * nrm - eo * nrmo);
                float inv_sd = rsqrtf(e * eo);         // 1/sqrt(e*eo)  (validated R11)
                float tau = __fdividef(dn * (0.5f * inv_sd), apq);
                float t = copysignf(1.f, tau) / (fabsf(tau) + sqrtf(fmaf(tau, tau, 1.f)));
                if (!rot) t = 0.f;
                float rr = eo * inv_sd;                // sqrt(eo/e)
                float al = (isp ? -t : t) * rr;        // g += al * h
                ull a2p = pack2(al, al);
#pragma unroll
                for (int i = 0; i < 16; i++)
                    gp[i] = fma2_(a2p, hp[i], gp[i]);
                float ct2 = fmaf(t, t, 1.f);           // 1/c^2
                nrm = fmaf(al, apq, nrm) * ct2;        // stored-norm update
                e = __fdividef(e, ct2);                // d'^2 = c^2 d^2
            }
        }
        // ---- fold scale back into the column; exact norm recompute -------
        float d = sqrtf(e);
        ull d2 = pack2(d, d);
        ull na0 = 0ull, na1 = 0ull;
#pragma unroll
        for (int i = 0; i < 16; i += 2) {
            gp[i]     = mul2_(gp[i],     d2);
            gp[i + 1] = mul2_(gp[i + 1], d2);
            na0 = fma2_(gp[i],     gp[i],     na0);
            na1 = fma2_(gp[i + 1], gp[i + 1], na1);
        }
        float nlo, nhi, mlo, mhi;
        unpack2(na0, nlo, nhi); unpack2(na1, mlo, mhi);
        nrm = (nlo + mlo) + (nhi + mhi);
        e = 1.f;
        if (!did) break;
    }

    // ---- epilogue: eigenvalue + eigenvector recovery ---------------------
    float gf[32];
#pragma unroll
    for (int i = 0; i < 16; i++) unpack2(gp[i], gf[2 * i], gf[2 * i + 1]);

    const float s2 = nrm;                        // ||g'||^2 (exact from fold)
    const float fj = sqrtf(__fdividef(1.f, s2) + 1e-6f);  // sqrt(lam + EPS)

    // stage g' column to smem (needed for dynamic-index recovery loop)
#pragma unroll
    for (int i = 0; i < 32; i++) Gsh[w][i][j] = gf[i];
    __syncwarp();

    // w = R^T g'; accw[i] = sum_m R[m][i] * g'_m
    float accw[32];
#pragma unroll
    for (int i = 0; i < 32; i++) accw[i] = 0.f;
    for (int m = 0; m < 32; m++) {
        float gm = Gsh[w][m][j];                 // own column, conflict-free
#pragma unroll
        for (int i = 0; i < 32; i++)
            accw[i] = fmaf(Bsh[w][m][i], gm, accw[i]);   // broadcast loads
    }
    float nn = 0.f;
#pragma unroll
    for (int i = 0; i < 32; i++) nn = fmaf(accw[i], accw[i], nn);
    phsh[w][j] = __fdividef(fj, nn);             // phi = f / ||w||^2
    __syncwarp();

    // overwrite Bsh with W (unscaled eigvec columns)
#pragma unroll
    for (int i = 0; i < 32; i++) Bsh[w][i][j] = accw[i];
    __syncwarp();

    // ---- out = sum_k phi_k * w_k w_k^T  (row j per lane) -----------------
    float accO[32];
#pragma unroll
    for (int i = 0; i < 32; i++) accO[i] = 0.f;
    for (int k = 0; k < 32; k++) {
        float qjk = Bsh[w][j][k] * phsh[w][k];   // stride-33: conflict-free
#pragma unroll
        for (int i = 0; i < 32; i++)
            accO[i] = fmaf(Bsh[w][i][k], qjk, accO[i]);  // broadcast loads
    }
    __syncwarp();
#pragma unroll
    for (int i = 0; i < 32; i++) Bsh[w][j][i] = accO[i];  // stage row j
    __syncwarp();

    float* ob = out + (size_t)b * 1024;
#pragma unroll
    for (int t = 0; t < 8; t++) {                // coalesced 512B stores
        int idx = t * 128 + j * 4;
        int rr = idx >> 5, cc = idx & 31;
        float4 val = make_float4(Bsh[w][rr][cc], Bsh[w][rr][cc + 1],
                                 Bsh[w][rr][cc + 2], Bsh[w][rr][cc + 3]);
        *(float4*)&ob[idx] = val;
    }
}

// ---------------------------------------------------------------------------
extern "C" void kernel_launch(void* const* d_in, const int* in_sizes, int n_in,
                              void* d_out, int out_size) {
    const float* x  = (const float*)d_in[0];
    const float* W1 = (const float*)d_in[1];
    const float* b1 = (const float*)d_in[2];
    const float* WD = (const float*)d_in[3];
    const float* bD = (const float*)d_in[4];
    const float* WV = (const float*)d_in[5];
    const float* bV = (const float*)d_in[6];
    float* out = (float*)d_out;

    dim3 g1(NH / 64, NB / 64);
    feat_kernel<<<g1, 256>>>(x, W1, b1);

    dim3 g2a(1, NB / 128);
    head_kernel<<<g2a, 256>>>(WD, bD, 32, 0);

    dim3 g2b((NY * NK) / 32, NB / 128);
    head_kernel<<<g2b, 256>>>(WV, bV, 256, 1);

    jacobi_kernel<<<NB / 4, 128>>>(out);
}

// round 15
// speedup vs baseline: 1.3887x; 1.0109x over previous
#include <cuda_runtime.h>
#include <math.h>

#define NB 16384
#define NIN 128
#define NH 512
#define NY 32
#define NK 8

static __device__ float g_feat[NB * NH];     // 32 MB scratch
static __device__ float g_D[NB * NY];        // 2 MB  (D = softplus+1e-3)
static __device__ float g_V[NB * NY * NK];   // 16 MB

typedef unsigned long long ull;

__device__ __forceinline__ ull pack2(float lo, float hi) {
    ull r; asm("mov.b64 %0, {%1, %2};" : "=l"(r) : "f"(lo), "f"(hi)); return r;
}
__device__ __forceinline__ void unpack2(ull v, float& lo, float& hi) {
    asm("mov.b64 {%0, %1}, %2;" : "=f"(lo), "=f"(hi) : "l"(v));
}
__device__ __forceinline__ ull fma2_(ull a, ull b, ull c) {
    ull d; asm("fma.rn.f32x2 %0, %1, %2, %3;" : "=l"(d) : "l"(a), "l"(b), "l"(c)); return d;
}
__device__ __forceinline__ ull mul2_(ull a, ull b) {
    ull d; asm("mul.rn.f32x2 %0, %1, %2;" : "=l"(d) : "l"(a), "l"(b)); return d;
}
__device__ __forceinline__ ull add2_(ull a, ull b) {
    ull d; asm("add.rn.f32x2 %0, %1, %2;" : "=l"(d) : "l"(a), "l"(b)); return d;
}

__device__ __forceinline__ float softplus_f(float v) {
    return (v > 20.f) ? v : log1pf(expf(v));
}

// ---------------------------------------------------------------------------
// K1: feat = relu(x @ W1 + b1)   [16384,128] @ [128,512]   (validated)
// ---------------------------------------------------------------------------
__global__ void __launch_bounds__(256) feat_kernel(const float* __restrict__ x,
                                                   const float* __restrict__ W1,
                                                   const float* __restrict__ b1) {
    __shared__ float Xs[32][68];
    __shared__ float Ws[32][68];
    const int bm = blockIdx.y * 64;
    const int bn = blockIdx.x * 64;
    const int tid = threadIdx.x;
    const int tx = tid & 15, ty = tid >> 4;

    float acc[4][4];
#pragma unroll
    for (int i = 0; i < 4; i++)
#pragma unroll
        for (int jj = 0; jj < 4; jj++) acc[i][jj] = 0.f;

    for (int k0 = 0; k0 < NIN; k0 += 32) {
#pragma unroll
        for (int t = 0; t < 8; t++) {
            int idx = tid + t * 256;
            int m = idx >> 5, k = idx & 31;
            Xs[k][m] = x[(size_t)(bm + m) * NIN + k0 + k];
        }
#pragma unroll
        for (int t = 0; t < 8; t++) {
            int idx = tid + t * 256;
            int k = idx >> 6, n = idx & 63;
            Ws[k][n] = W1[(size_t)(k0 + k) * NH + bn + n];
        }
        __syncthreads();
#pragma unroll
        for (int k = 0; k < 32; k++) {
            float4 a  = *(const float4*)&Xs[k][ty * 4];
            float4 bq = *(const float4*)&Ws[k][tx * 4];
            float av[4] = {a.x, a.y, a.z, a.w};
            float bv[4] = {bq.x, bq.y, bq.z, bq.w};
#pragma unroll
            for (int i = 0; i < 4; i++)
#pragma unroll
                for (int jj = 0; jj < 4; jj++)
                    acc[i][jj] = fmaf(av[i], bv[jj], acc[i][jj]);
        }
        __syncthreads();
    }
#pragma unroll
    for (int i = 0; i < 4; i++) {
        int m = bm + ty * 4 + i;
#pragma unroll
        for (int jj = 0; jj < 4; jj++) {
            int n = bn + tx * 4 + jj;
            float v = acc[i][jj] + b1[n];
            g_feat[(size_t)m * NH + n] = fmaxf(v, 0.f);
        }
    }
}

// ---------------------------------------------------------------------------
// K2 (fused heads): blockIdx.x == 0 -> D = softplus(feat@WD+bD)+1e-3 (N=32)
//                   blockIdx.x 1..8 -> V tile bn=(bx-1)*32 of feat@WV+bV
// Identical inner structure to the validated head_kernel; only a block-scope
// pointer/ld select differs.
// ---------------------------------------------------------------------------
__global__ void __launch_bounds__(256) heads_kernel(const float* __restrict__ WD,
                                                    const float* __restrict__ bD,
                                                    const float* __restrict__ WV,
                                                    const float* __restrict__ bV) {
    __shared__ float Fs[32][132];
    __shared__ float Ws2[32][36];
    const int bx = blockIdx.x;
    const int isD = (bx == 0);
    const float* Wmat = isD ? WD : WV;
    const float* bias = isD ? bD : bV;
    const int ldw = isD ? NY : (NY * NK);
    const int bn = isD ? 0 : (bx - 1) * 32;
    const int bm = blockIdx.y * 128;
    const int tid = threadIdx.x;
    const int tx = tid & 7, ty = tid >> 3;

    float acc[4][4];
#pragma unroll
    for (int i = 0; i < 4; i++)
#pragma unroll
        for (int jj = 0; jj < 4; jj++) acc[i][jj] = 0.f;

    for (int k0 = 0; k0 < NH; k0 += 32) {
#pragma unroll
        for (int t = 0; t < 16; t++) {
            int idx = tid + t * 256;
            int m = idx >> 5, k = idx & 31;
            Fs[k][m] = g_feat[(size_t)(bm + m) * NH + k0 + k];
        }
#pragma unroll
        for (int t = 0; t < 4; t++) {
            int idx = tid + t * 256;
            int k = idx >> 5, n = idx & 31;
            Ws2[k][n] = Wmat[(size_t)(k0 + k) * ldw + bn + n];
        }
        __syncthreads();
#pragma unroll
        for (int k = 0; k < 32; k++) {
            float4 a  = *(const float4*)&Fs[k][ty * 4];
            float4 bq = *(const float4*)&Ws2[k][tx * 4];
            float av[4] = {a.x, a.y, a.z, a.w};
            float bv[4] = {bq.x, bq.y, bq.z, bq.w};
#pragma unroll
            for (int i = 0; i < 4; i++)
#pragma unroll
                for (int jj = 0; jj < 4; jj++)
                    acc[i][jj] = fmaf(av[i], bv[jj], acc[i][jj]);
        }
        __syncthreads();
    }
#pragma unroll
    for (int i = 0; i < 4; i++) {
        int m = bm + ty * 4 + i;
#pragma unroll
        for (int jj = 0; jj < 4; jj++) {
            int n = bn + tx * 4 + jj;
            float v = acc[i][jj] + bias[n];
            if (isD) {
                g_D[(size_t)m * NY + n] = softplus_f(v) + 1e-3f;
            } else {
                g_V[(size_t)m * (NY * NK) + n] = v;
            }
        }
    }
}

// ---------------------------------------------------------------------------
// K3: Givens-QR compresses G = [diag(D); V^T] (40x32) to upper-triangular
// R (32x32), then one-sided Jacobi on 32-length register columns.
// (128,6): 24 warps/SM, no hot-loop spills (R11 proved (128,7) harmful).
// ---------------------------------------------------------------------------
__global__ void __launch_bounds__(128, 6) jacobi_kernel(float* __restrict__ out) {
    __shared__ float Bsh[4][32][33];   // R -> W (eigvecs) -> output rows
    __shared__ float Gsh[4][32][33];   // converged g' columns
    __shared__ float phsh[4][32];

    const int w = threadIdx.x >> 5;
    const int j = threadIdx.x & 31;
    const int b = blockIdx.x * 4 + w;
    const unsigned FULL = 0xffffffffu;

    // ---- load column j of G: top = D_j e_j, bottom = V[j][:] -------------
    const float Dj = g_D[(size_t)b * NY + j];
    const float4 v0 = *(const float4*)&g_V[(size_t)b * 256 + j * 8];
    const float4 v1 = *(const float4*)&g_V[(size_t)b * 256 + j * 8 + 4];

    float tf[32];
#pragma unroll
    for (int i = 0; i < 32; i++) tf[i] = (i == j) ? Dj : 0.f;
    float bt[8] = {v0.x, v0.y, v0.z, v0.w, v1.x, v1.y, v1.z, v1.w};

    // ---- Givens QR: zero the 8 bottom rows --------------------------------
#pragma unroll
    for (int jj = 0; jj < 32; jj++) {
#pragma unroll
        for (int k = 0; k < 8; k++) {
            float a, bb;
            { ull ab = __shfl_sync(FULL, pack2(tf[jj], bt[k]), jj);
              unpack2(ab, a, bb); }
            // pivot a = R[jj][jj] >= D_jj >= 1e-3 > 0 always
            float rinv = rsqrtf(fmaf(a, a, bb * bb));
            float c = a * rinv, s = bb * rinv;
            float t1 = fmaf(c, tf[jj], s * bt[k]);
            bt[k]  = fmaf(c, bt[k], -s * tf[jj]);
            tf[jj] = t1;
        }
    }

    // ---- stage R to smem (column j), compute column norm ------------------
    float nrm = 0.f;
#pragma unroll
    for (int i = 0; i < 32; i++) {
        Bsh[w][i][j] = tf[i];
        nrm = fmaf(tf[i], tf[i], nrm);
    }
    __syncwarp();

    // ---- pack into 16 f32x2 registers -------------------------------------
    ull gp[16];
#pragma unroll
    for (int i = 0; i < 16; i++) gp[i] = pack2(tf[2 * i], tf[2 * i + 1]);

    float e = 1.f;                              // column scale^2 (d^2)
    const float tol2 = 1e-11f;                  // (~3e-6)^2 relative (validated)

    // ---- one-sided Jacobi sweeps (XOR tournament: m = 1..31) -------------
    for (int sweep = 0; sweep < 12; sweep++) {
        int did = 0;
        for (int m = 1; m < 32; m++) {
            // fetch partner column ONCE (reused for dot + update)
            ull hp[16];
#pragma unroll
            for (int i = 0; i < 16; i++)
                hp[i] = __shfl_xor_sync(FULL, gp[i], m);
            float nrmo, eo;
            { ull neo = __shfl_xor_sync(FULL, pack2(nrm, e), m);
              unpack2(neo, nrmo, eo); }

            // dot: a_pq(stored), 4 accumulators, packed add-tree reduce
            ull a0 = 0ull, a1 = 0ull, a2v = 0ull, a3 = 0ull;
#pragma unroll
            for (int i = 0; i < 16; i += 4) {
                a0  = fma2_(gp[i],     hp[i],     a0);
                a1  = fma2_(gp[i + 1], hp[i + 1], a1);
                a2v = fma2_(gp[i + 2], hp[i + 2], a2v);
                a3  = fma2_(gp[i + 3], hp[i + 3], a3);
            }
            ull sred = add2_(add2_(a0, a1), add2_(a2v, a3));
            float slo, shi;
            unpack2(sred, slo, shi);
            float apq = slo + shi;

            // scale-invariant threshold
            bool rot = apq * apq > tol2 * nrm * nrmo;
            if (__any_sync(FULL, rot)) {
                did = 1;
                bool isp = j < (j ^ m);
                // tau = (aqq - app)_true / (2*apq_true); same on both lanes
                float dn = isp ? (eo * nrmo - e * nrm) : (e * nrm - eo * nrmo);
                float inv_sd = rsqrtf(e * eo);         // 1/sqrt(e*eo)  (validated)
                float tau = __fdividef(dn * (0.5f * inv_sd), apq);
                float t = __fdividef(copysignf(1.f, tau),
                                     fabsf(tau) + sqrtf(fmaf(tau, tau, 1.f)));
                if (!rot) t = 0.f;
                float rr = eo * inv_sd;                // sqrt(eo/e)
                float al = (isp ? -t : t) * rr;        // g += al * h
                ull a2p = pack2(al, al);
#pragma unroll
                for (int i = 0; i < 16; i++)
                    gp[i] = fma2_(a2p, hp[i], gp[i]);
                float ct2 = fmaf(t, t, 1.f);           // 1/c^2
                nrm = fmaf(al, apq, nrm) * ct2;        // stored-norm update
                e = __fdividef(e, ct2);                // d'^2 = c^2 d^2
            }
        }
        // ---- fold scale back into the column; exact norm recompute -------
        float d = sqrtf(e);
        ull d2 = pack2(d, d);
        ull na0 = 0ull, na1 = 0ull;
#pragma unroll
        for (int i = 0; i < 16; i += 2) {
            gp[i]     = mul2_(gp[i],     d2);
            gp[i + 1] = mul2_(gp[i + 1], d2);
            na0 = fma2_(gp[i],     gp[i],     na0);
            na1 = fma2_(gp[i + 1], gp[i + 1], na1);
        }
        float nlo, nhi, mlo, mhi;
        unpack2(na0, nlo, nhi); unpack2(na1, mlo, mhi);
        nrm = (nlo + mlo) + (nhi + mhi);
        e = 1.f;
        if (!did) break;
    }

    // ---- epilogue: eigenvalue + eigenvector recovery ---------------------
    float gf[32];
#pragma unroll
    for (int i = 0; i < 16; i++) unpack2(gp[i], gf[2 * i], gf[2 * i + 1]);

    const float s2 = nrm;                        // ||g'||^2 (exact from fold)
    const float fj = sqrtf(__fdividef(1.f, s2) + 1e-6f);  // sqrt(lam + EPS)

    // stage g' column to smem (needed for dynamic-index recovery loop)
#pragma unroll
    for (int i = 0; i < 32; i++) Gsh[w][i][j] = gf[i];
    __syncwarp();

    // w = R^T g'; accw[i] = sum_m R[m][i] * g'_m
    float accw[32];
#pragma unroll
    for (int i = 0; i < 32; i++) accw[i] = 0.f;
    for (int m = 0; m < 32; m++) {
        float gm = Gsh[w][m][j];                 // own column, conflict-free
#pragma unroll
        for (int i = 0; i < 32; i++)
            accw[i] = fmaf(Bsh[w][m][i], gm, accw[i]);   // broadcast loads
    }
    float nn = 0.f;
#pragma unroll
    for (int i = 0; i < 32; i++) nn = fmaf(accw[i], accw[i], nn);
    phsh[w][j] = __fdividef(fj, nn);             // phi = f / ||w||^2
    __syncwarp();

    // overwrite Bsh with W (unscaled eigvec columns)
#pragma unroll
    for (int i = 0; i < 32; i++) Bsh[w][i][j] = accw[i];
    __syncwarp();

    // ---- out = sum_k phi_k * w_k w_k^T  (row j per lane) -----------------
    float accO[32];
#pragma unroll
    for (int i = 0; i < 32; i++) accO[i] = 0.f;
    for (int k = 0; k < 32; k++) {
        float qjk = Bsh[w][j][k] * phsh[w][k];   // stride-33: conflict-free
#pragma unroll
        for (int i = 0; i < 32; i++)
            accO[i] = fmaf(Bsh[w][i][k], qjk, accO[i]);  // broadcast loads
    }
    __syncwarp();
#pragma unroll
    for (int i = 0; i < 32; i++) Bsh[w][j][i] = accO[i];  // stage row j
    __syncwarp();

    float* ob = out + (size_t)b * 1024;
#pragma unroll
    for (int t = 0; t < 8; t++) {                // coalesced 512B stores
        int idx = t * 128 + j * 4;
        int rr = idx >> 5, cc = idx & 31;
        float4 val = make_float4(Bsh[w][rr][cc], Bsh[w][rr][cc + 1],
                                 Bsh[w][rr][cc + 2], Bsh[w][rr][cc + 3]);
        *(float4*)&ob[idx] = val;
    }
}

// ---------------------------------------------------------------------------
extern "C" void kernel_launch(void* const* d_in, const int* in_sizes, int n_in,
                              void* d_out, int out_size) {
    const float* x  = (const float*)d_in[0];
    const float* W1 = (const float*)d_in[1];
    const float* b1 = (const float*)d_in[2];
    const float* WD = (const float*)d_in[3];
    const float* bD = (const float*)d_in[4];
    const float* WV = (const float*)d_in[5];
    const float* bV = (const float*)d_in[6];
    float* out = (float*)d_out;

    dim3 g1(NH / 64, NB / 64);
    feat_kernel<<<g1, 256>>>(x, W1, b1);

    dim3 g2(9, NB / 128);                        // bx=0: D head, bx=1..8: V
    heads_kernel<<<g2, 256>>>(WD, bD, WV, bV);

    jacobi_kernel<<<NB / 4, 128>>>(out);
}

// round 16
// speedup vs baseline: 1.5141x; 1.0903x over previous
#include <cuda_runtime.h>
#include <math.h>

#define NB 16384
#define NIN 128
#define NH 512
#define NY 32
#define NK 8

static __device__ float g_feat[NB * NH];     // 32 MB scratch
static __device__ float g_D[NB * NY];        // 2 MB  (D = softplus+1e-3)
static __device__ float g_V[NB * NY * NK];   // 16 MB

typedef unsigned long long ull;

__device__ __forceinline__ ull pack2(float lo, float hi) {
    ull r; asm("mov.b64 %0, {%1, %2};" : "=l"(r) : "f"(lo), "f"(hi)); return r;
}
__device__ __forceinline__ void unpack2(ull v, float& lo, float& hi) {
    asm("mov.b64 {%0, %1}, %2;" : "=f"(lo), "=f"(hi) : "l"(v));
}
__device__ __forceinline__ ull fma2_(ull a, ull b, ull c) {
    ull d; asm("fma.rn.f32x2 %0, %1, %2, %3;" : "=l"(d) : "l"(a), "l"(b), "l"(c)); return d;
}
__device__ __forceinline__ ull mul2_(ull a, ull b) {
    ull d; asm("mul.rn.f32x2 %0, %1, %2;" : "=l"(d) : "l"(a), "l"(b)); return d;
}
__device__ __forceinline__ ull add2_(ull a, ull b) {
    ull d; asm("add.rn.f32x2 %0, %1, %2;" : "=l"(d) : "l"(a), "l"(b)); return d;
}

__device__ __forceinline__ float softplus_f(float v) {
    return (v > 20.f) ? v : log1pf(expf(v));
}

// ---------------------------------------------------------------------------
// K1: feat = relu(x @ W1 + b1)   [16384,128] @ [128,512]   (validated)
// ---------------------------------------------------------------------------
__global__ void __launch_bounds__(256) feat_kernel(const float* __restrict__ x,
                                                   const float* __restrict__ W1,
                                                   const float* __restrict__ b1) {
    __shared__ float Xs[32][68];
    __shared__ float Ws[32][68];
    const int bm = blockIdx.y * 64;
    const int bn = blockIdx.x * 64;
    const int tid = threadIdx.x;
    const int tx = tid & 15, ty = tid >> 4;

    float acc[4][4];
#pragma unroll
    for (int i = 0; i < 4; i++)
#pragma unroll
        for (int jj = 0; jj < 4; jj++) acc[i][jj] = 0.f;

    for (int k0 = 0; k0 < NIN; k0 += 32) {
#pragma unroll
        for (int t = 0; t < 8; t++) {
            int idx = tid + t * 256;
            int m = idx >> 5, k = idx & 31;
            Xs[k][m] = x[(size_t)(bm + m) * NIN + k0 + k];
        }
#pragma unroll
        for (int t = 0; t < 8; t++) {
            int idx = tid + t * 256;
            int k = idx >> 6, n = idx & 63;
            Ws[k][n] = W1[(size_t)(k0 + k) * NH + bn + n];
        }
        __syncthreads();
#pragma unroll
        for (int k = 0; k < 32; k++) {
            float4 a  = *(const float4*)&Xs[k][ty * 4];
            float4 bq = *(const float4*)&Ws[k][tx * 4];
            float av[4] = {a.x, a.y, a.z, a.w};
            float bv[4] = {bq.x, bq.y, bq.z, bq.w};
#pragma unroll
            for (int i = 0; i < 4; i++)
#pragma unroll
                for (int jj = 0; jj < 4; jj++)
                    acc[i][jj] = fmaf(av[i], bv[jj], acc[i][jj]);
        }
        __syncthreads();
    }
#pragma unroll
    for (int i = 0; i < 4; i++) {
        int m = bm + ty * 4 + i;
#pragma unroll
        for (int jj = 0; jj < 4; jj++) {
            int n = bn + tx * 4 + jj;
            float v = acc[i][jj] + b1[n];
            g_feat[(size_t)m * NH + n] = fmaxf(v, 0.f);
        }
    }
}

// ---------------------------------------------------------------------------
// K2 (fused heads): blockIdx.x == 0 -> D = softplus(feat@WD+bD)+1e-3 (N=32)
//                   blockIdx.x 1..8 -> V tile bn=(bx-1)*32 of feat@WV+bV
// (validated R14)
// ---------------------------------------------------------------------------
__global__ void __launch_bounds__(256) heads_kernel(const float* __restrict__ WD,
                                                    const float* __restrict__ bD,
                                                    const float* __restrict__ WV,
                                                    const float* __restrict__ bV) {
    __shared__ float Fs[32][132];
    __shared__ float Ws2[32][36];
    const int bx = blockIdx.x;
    const int isD = (bx == 0);
    const float* Wmat = isD ? WD : WV;
    const float* bias = isD ? bD : bV;
    const int ldw = isD ? NY : (NY * NK);
    const int bn = isD ? 0 : (bx - 1) * 32;
    const int bm = blockIdx.y * 128;
    const int tid = threadIdx.x;
    const int tx = tid & 7, ty = tid >> 3;

    float acc[4][4];
#pragma unroll
    for (int i = 0; i < 4; i++)
#pragma unroll
        for (int jj = 0; jj < 4; jj++) acc[i][jj] = 0.f;

    for (int k0 = 0; k0 < NH; k0 += 32) {
#pragma unroll
        for (int t = 0; t < 16; t++) {
            int idx = tid + t * 256;
            int m = idx >> 5, k = idx & 31;
            Fs[k][m] = g_feat[(size_t)(bm + m) * NH + k0 + k];
        }
#pragma unroll
        for (int t = 0; t < 4; t++) {
            int idx = tid + t * 256;
            int k = idx >> 5, n = idx & 31;
            Ws2[k][n] = Wmat[(size_t)(k0 + k) * ldw + bn + n];
        }
        __syncthreads();
#pragma unroll
        for (int k = 0; k < 32; k++) {
            float4 a  = *(const float4*)&Fs[k][ty * 4];
            float4 bq = *(const float4*)&Ws2[k][tx * 4];
            float av[4] = {a.x, a.y, a.z, a.w};
            float bv[4] = {bq.x, bq.y, bq.z, bq.w};
#pragma unroll
            for (int i = 0; i < 4; i++)
#pragma unroll
                for (int jj = 0; jj < 4; jj++)
                    acc[i][jj] = fmaf(av[i], bv[jj], acc[i][jj]);
        }
        __syncthreads();
    }
#pragma unroll
    for (int i = 0; i < 4; i++) {
        int m = bm + ty * 4 + i;
#pragma unroll
        for (int jj = 0; jj < 4; jj++) {
            int n = bn + tx * 4 + jj;
            float v = acc[i][jj] + bias[n];
            if (isD) {
                g_D[(size_t)m * NY + n] = softplus_f(v) + 1e-3f;
            } else {
                g_V[(size_t)m * (NY * NK) + n] = v;
            }
        }
    }
}

// ---------------------------------------------------------------------------
// K3: Givens-QR compresses G = [diag(D); V^T] (40x32) to upper-triangular
// R (32x32), then one-sided Jacobi on 32-length register columns.
// Changes vs R14 (validated base): tol2 1e-11 -> 1e-10 (single numeric
// variable; ~1 fewer sweep); Gsh eliminated (recovery statically unrolled
// from registers).
// ---------------------------------------------------------------------------
__global__ void __launch_bounds__(128, 6) jacobi_kernel(float* __restrict__ out) {
    __shared__ float Bsh[4][32][33];   // R -> W (eigvecs) -> output rows
    __shared__ float phsh[4][32];

    const int w = threadIdx.x >> 5;
    const int j = threadIdx.x & 31;
    const int b = blockIdx.x * 4 + w;
    const unsigned FULL = 0xffffffffu;

    // ---- load column j of G: top = D_j e_j, bottom = V[j][:] -------------
    const float Dj = g_D[(size_t)b * NY + j];
    const float4 v0 = *(const float4*)&g_V[(size_t)b * 256 + j * 8];
    const float4 v1 = *(const float4*)&g_V[(size_t)b * 256 + j * 8 + 4];

    float tf[32];
#pragma unroll
    for (int i = 0; i < 32; i++) tf[i] = (i == j) ? Dj : 0.f;
    float bt[8] = {v0.x, v0.y, v0.z, v0.w, v1.x, v1.y, v1.z, v1.w};

    // ---- Givens QR: zero the 8 bottom rows --------------------------------
#pragma unroll
    for (int jj = 0; jj < 32; jj++) {
#pragma unroll
        for (int k = 0; k < 8; k++) {
            float a, bb;
            { ull ab = __shfl_sync(FULL, pack2(tf[jj], bt[k]), jj);
              unpack2(ab, a, bb); }
            // pivot a = R[jj][jj] >= D_jj >= 1e-3 > 0 always
            float rinv = rsqrtf(fmaf(a, a, bb * bb));
            float c = a * rinv, s = bb * rinv;
            float t1 = fmaf(c, tf[jj], s * bt[k]);
            bt[k]  = fmaf(c, bt[k], -s * tf[jj]);
            tf[jj] = t1;
        }
    }

    // ---- stage R to smem (column j), compute column norm ------------------
    float nrm = 0.f;
#pragma unroll
    for (int i = 0; i < 32; i++) {
        Bsh[w][i][j] = tf[i];
        nrm = fmaf(tf[i], tf[i], nrm);
    }
    __syncwarp();

    // ---- pack into 16 f32x2 registers -------------------------------------
    ull gp[16];
#pragma unroll
    for (int i = 0; i < 16; i++) gp[i] = pack2(tf[2 * i], tf[2 * i + 1]);

    float e = 1.f;                              // column scale^2 (d^2)
    const float tol2 = 1e-10f;                  // (~1e-5)^2 relative

    // ---- one-sided Jacobi sweeps (XOR tournament: m = 1..31) -------------
    for (int sweep = 0; sweep < 10; sweep++) {
        int did = 0;
        for (int m = 1; m < 32; m++) {
            // fetch partner column ONCE (reused for dot + update)
            ull hp[16];
#pragma unroll
            for (int i = 0; i < 16; i++)
                hp[i] = __shfl_xor_sync(FULL, gp[i], m);
            float nrmo, eo;
            { ull neo = __shfl_xor_sync(FULL, pack2(nrm, e), m);
              unpack2(neo, nrmo, eo); }

            // dot: a_pq(stored), 4 accumulators, packed add-tree reduce
            ull a0 = 0ull, a1 = 0ull, a2v = 0ull, a3 = 0ull;
#pragma unroll
            for (int i = 0; i < 16; i += 4) {
                a0  = fma2_(gp[i],     hp[i],     a0);
                a1  = fma2_(gp[i + 1], hp[i + 1], a1);
                a2v = fma2_(gp[i + 2], hp[i + 2], a2v);
                a3  = fma2_(gp[i + 3], hp[i + 3], a3);
            }
            ull sred = add2_(add2_(a0, a1), add2_(a2v, a3));
            float slo, shi;
            unpack2(sred, slo, shi);
            float apq = slo + shi;

            // scale-invariant threshold
            bool rot = apq * apq > tol2 * nrm * nrmo;
            if (__any_sync(FULL, rot)) {
                did = 1;
                bool isp = j < (j ^ m);
                // tau = (aqq - app)_true / (2*apq_true); same on both lanes
                float dn = isp ? (eo * nrmo - e * nrm) : (e * nrm - eo * nrmo);
                float inv_sd = rsqrtf(e * eo);         // 1/sqrt(e*eo)  (validated)
                float tau = __fdividef(dn * (0.5f * inv_sd), apq);
                float t = __fdividef(copysignf(1.f, tau),
                                     fabsf(tau) + sqrtf(fmaf(tau, tau, 1.f)));
                if (!rot) t = 0.f;
                float rr = eo * inv_sd;                // sqrt(eo/e)
                float al = (isp ? -t : t) * rr;        // g += al * h
                ull a2p = pack2(al, al);
#pragma unroll
                for (int i = 0; i < 16; i++)
                    gp[i] = fma2_(a2p, hp[i], gp[i]);
                float ct2 = fmaf(t, t, 1.f);           // 1/c^2
                nrm = fmaf(al, apq, nrm) * ct2;        // stored-norm update
                e = __fdividef(e, ct2);                // d'^2 = c^2 d^2
            }
        }
        // ---- fold scale back into the column; exact norm recompute -------
        float d = sqrtf(e);
        ull d2 = pack2(d, d);
        ull na0 = 0ull, na1 = 0ull;
#pragma unroll
        for (int i = 0; i < 16; i += 2) {
            gp[i]     = mul2_(gp[i],     d2);
            gp[i + 1] = mul2_(gp[i + 1], d2);
            na0 = fma2_(gp[i],     gp[i],     na0);
            na1 = fma2_(gp[i + 1], gp[i + 1], na1);
        }
        float nlo, nhi, mlo, mhi;
        unpack2(na0, nlo, nhi); unpack2(na1, mlo, mhi);
        nrm = (nlo + mlo) + (nhi + mhi);
        e = 1.f;
        if (!did) break;
    }

    // ---- epilogue: eigenvalue + eigenvector recovery ---------------------
    float gf[32];
#pragma unroll
    for (int i = 0; i < 16; i++) unpack2(gp[i], gf[2 * i], gf[2 * i + 1]);

    const float s2 = nrm;                        // ||g'||^2 (exact from fold)
    const float fj = sqrtf(__fdividef(1.f, s2) + 1e-6f);  // sqrt(lam + EPS)

    // w = R^T g'  (g' fully register-resident; statically unrolled)
    float accw[32];
#pragma unroll
    for (int i = 0; i < 32; i++) accw[i] = 0.f;
#pragma unroll
    for (int m = 0; m < 32; m++) {
        float gm = gf[m];                        // register, static index
#pragma unroll
        for (int i = 0; i < 32; i++)
            accw[i] = fmaf(Bsh[w][m][i], gm, accw[i]);   // broadcast loads
    }
    float nn = 0.f;
#pragma unroll
    for (int i = 0; i < 32; i++) nn = fmaf(accw[i], accw[i], nn);
    phsh[w][j] = __fdividef(fj, nn);             // phi = f / ||w||^2
    __syncwarp();

    // overwrite Bsh with W (unscaled eigvec columns)
#pragma unroll
    for (int i = 0; i < 32; i++) Bsh[w][i][j] = accw[i];
    __syncwarp();

    // ---- out = sum_k phi_k * w_k w_k^T  (row j per lane) -----------------
    float accO[32];
#pragma unroll
    for (int i = 0; i < 32; i++) accO[i] = 0.f;
    for (int k = 0; k < 32; k++) {
        float qjk = Bsh[w][j][k] * phsh[w][k];   // stride-33: conflict-free
#pragma unroll
        for (int i = 0; i < 32; i++)
            accO[i] = fmaf(Bsh[w][i][k], qjk, accO[i]);  // broadcast loads
    }
    __syncwarp();
#pragma unroll
    for (int i = 0; i < 32; i++) Bsh[w][j][i] = accO[i];  // stage row j
    __syncwarp();

    float* ob = out + (size_t)b * 1024;
#pragma unroll
    for (int t = 0; t < 8; t++) {                // coalesced 512B stores
        int idx = t * 128 + j * 4;
        int rr = idx >> 5, cc = idx & 31;
        float4 val = make_float4(Bsh[w][rr][cc], Bsh[w][rr][cc + 1],
                                 Bsh[w][rr][cc + 2], Bsh[w][rr][cc + 3]);
        *(float4*)&ob[idx] = val;
    }
}

// ---------------------------------------------------------------------------
extern "C" void kernel_launch(void* const* d_in, const int* in_sizes, int n_in,
                              void* d_out, int out_size) {
    const float* x  = (const float*)d_in[0];
    const float* W1 = (const float*)d_in[1];
    const float* b1 = (const float*)d_in[2];
    const float* WD = (const float*)d_in[3];
    const float* bD = (const float*)d_in[4];
    const float* WV = (const float*)d_in[5];
    const float* bV = (const float*)d_in[6];
    float* out = (float*)d_out;

    dim3 g1(NH / 64, NB / 64);
    feat_kernel<<<g1, 256>>>(x, W1, b1);

    dim3 g2(9, NB / 128);                        // bx=0: D head, bx=1..8: V
    heads_kernel<<<g2, 256>>>(WD, bD, WV, bV);

    jacobi_kernel<<<NB / 4, 128>>>(out);
}

// round 17
// speedup vs baseline: 1.5375x; 1.0155x over previous
#include <cuda_runtime.h>
#include <math.h>

#define NB 16384
#define NIN 128
#define NH 512
#define NY 32
#define NK 8

static __device__ float g_feat[NB * NH];     // 32 MB scratch
static __device__ float g_D[NB * NY];        // 2 MB  (D = softplus+1e-3)
static __device__ float g_V[NB * NY * NK];   // 16 MB

typedef unsigned long long ull;

__device__ __forceinline__ ull pack2(float lo, float hi) {
    ull r; asm("mov.b64 %0, {%1, %2};" : "=l"(r) : "f"(lo), "f"(hi)); return r;
}
__device__ __forceinline__ void unpack2(ull v, float& lo, float& hi) {
    asm("mov.b64 {%0, %1}, %2;" : "=f"(lo), "=f"(hi) : "l"(v));
}
__device__ __forceinline__ ull fma2_(ull a, ull b, ull c) {
    ull d; asm("fma.rn.f32x2 %0, %1, %2, %3;" : "=l"(d) : "l"(a), "l"(b), "l"(c)); return d;
}
__device__ __forceinline__ ull mul2_(ull a, ull b) {
    ull d; asm("mul.rn.f32x2 %0, %1, %2;" : "=l"(d) : "l"(a), "l"(b)); return d;
}
__device__ __forceinline__ ull add2_(ull a, ull b) {
    ull d; asm("add.rn.f32x2 %0, %1, %2;" : "=l"(d) : "l"(a), "l"(b)); return d;
}

__device__ __forceinline__ float softplus_f(float v) {
    return (v > 20.f) ? v : log1pf(expf(v));
}

// ---------------------------------------------------------------------------
// K1: feat = relu(x @ W1 + b1)   [16384,128] @ [128,512]   (validated)
// ---------------------------------------------------------------------------
__global__ void __launch_bounds__(256) feat_kernel(const float* __restrict__ x,
                                                   const float* __restrict__ W1,
                                                   const float* __restrict__ b1) {
    __shared__ float Xs[32][68];
    __shared__ float Ws[32][68];
    const int bm = blockIdx.y * 64;
    const int bn = blockIdx.x * 64;
    const int tid = threadIdx.x;
    const int tx = tid & 15, ty = tid >> 4;

    float acc[4][4];
#pragma unroll
    for (int i = 0; i < 4; i++)
#pragma unroll
        for (int jj = 0; jj < 4; jj++) acc[i][jj] = 0.f;

    for (int k0 = 0; k0 < NIN; k0 += 32) {
#pragma unroll
        for (int t = 0; t < 8; t++) {
            int idx = tid + t * 256;
            int m = idx >> 5, k = idx & 31;
            Xs[k][m] = x[(size_t)(bm + m) * NIN + k0 + k];
        }
#pragma unroll
        for (int t = 0; t < 8; t++) {
            int idx = tid + t * 256;
            int k = idx >> 6, n = idx & 63;
            Ws[k][n] = W1[(size_t)(k0 + k) * NH + bn + n];
        }
        __syncthreads();
#pragma unroll
        for (int k = 0; k < 32; k++) {
            float4 a  = *(const float4*)&Xs[k][ty * 4];
            float4 bq = *(const float4*)&Ws[k][tx * 4];
            float av[4] = {a.x, a.y, a.z, a.w};
            float bv[4] = {bq.x, bq.y, bq.z, bq.w};
#pragma unroll
            for (int i = 0; i < 4; i++)
#pragma unroll
                for (int jj = 0; jj < 4; jj++)
                    acc[i][jj] = fmaf(av[i], bv[jj], acc[i][jj]);
        }
        __syncthreads();
    }
#pragma unroll
    for (int i = 0; i < 4; i++) {
        int m = bm + ty * 4 + i;
#pragma unroll
        for (int jj = 0; jj < 4; jj++) {
            int n = bn + tx * 4 + jj;
            float v = acc[i][jj] + b1[n];
            g_feat[(size_t)m * NH + n] = fmaxf(v, 0.f);
        }
    }
}

// ---------------------------------------------------------------------------
// K2 (fused heads): blockIdx.x == 0 -> D = softplus(feat@WD+bD)+1e-3 (N=32)
//                   blockIdx.x 1..8 -> V tile bn=(bx-1)*32 of feat@WV+bV
// (validated R14/R15)
// ---------------------------------------------------------------------------
__global__ void __launch_bounds__(256) heads_kernel(const float* __restrict__ WD,
                                                    const float* __restrict__ bD,
                                                    const float* __restrict__ WV,
                                                    const float* __restrict__ bV) {
    __shared__ float Fs[32][132];
    __shared__ float Ws2[32][36];
    const int bx = blockIdx.x;
    const int isD = (bx == 0);
    const float* Wmat = isD ? WD : WV;
    const float* bias = isD ? bD : bV;
    const int ldw = isD ? NY : (NY * NK);
    const int bn = isD ? 0 : (bx - 1) * 32;
    const int bm = blockIdx.y * 128;
    const int tid = threadIdx.x;
    const int tx = tid & 7, ty = tid >> 3;

    float acc[4][4];
#pragma unroll
    for (int i = 0; i < 4; i++)
#pragma unroll
        for (int jj = 0; jj < 4; jj++) acc[i][jj] = 0.f;

    for (int k0 = 0; k0 < NH; k0 += 32) {
#pragma unroll
        for (int t = 0; t < 16; t++) {
            int idx = tid + t * 256;
            int m = idx >> 5, k = idx & 31;
            Fs[k][m] = g_feat[(size_t)(bm + m) * NH + k0 + k];
        }
#pragma unroll
        for (int t = 0; t < 4; t++) {
            int idx = tid + t * 256;
            int k = idx >> 5, n = idx & 31;
            Ws2[k][n] = Wmat[(size_t)(k0 + k) * ldw + bn + n];
        }
        __syncthreads();
#pragma unroll
        for (int k = 0; k < 32; k++) {
            float4 a  = *(const float4*)&Fs[k][ty * 4];
            float4 bq = *(const float4*)&Ws2[k][tx * 4];
            float av[4] = {a.x, a.y, a.z, a.w};
            float bv[4] = {bq.x, bq.y, bq.z, bq.w};
#pragma unroll
            for (int i = 0; i < 4; i++)
#pragma unroll
                for (int jj = 0; jj < 4; jj++)
                    acc[i][jj] = fmaf(av[i], bv[jj], acc[i][jj]);
        }
        __syncthreads();
    }
#pragma unroll
    for (int i = 0; i < 4; i++) {
        int m = bm + ty * 4 + i;
#pragma unroll
        for (int jj = 0; jj < 4; jj++) {
            int n = bn + tx * 4 + jj;
            float v = acc[i][jj] + bias[n];
            if (isD) {
                g_D[(size_t)m * NY + n] = softplus_f(v) + 1e-3f;
            } else {
                g_V[(size_t)m * (NY * NK) + n] = v;
            }
        }
    }
}

// ---------------------------------------------------------------------------
// K3: Givens-QR compresses G = [diag(D); V^T] (40x32) to upper-triangular
// R (32x32), then one-sided Jacobi on 32-length register columns.
// Changes vs R15 (validated base):
//   - tol2 1e-10 -> 3e-10 (single numeric variable; rel_err model ~11*tau)
//   - recovery w = R^T g' exploits exact upper-triangularity of R
//     (sub-diagonal zeros are exact: produced as c*0+s*0 in the QR)
// ---------------------------------------------------------------------------
__global__ void __launch_bounds__(128, 6) jacobi_kernel(float* __restrict__ out) {
    __shared__ float Bsh[4][32][33];   // R -> W (eigvecs) -> output rows
    __shared__ float phsh[4][32];

    const int w = threadIdx.x >> 5;
    const int j = threadIdx.x & 31;
    const int b = blockIdx.x * 4 + w;
    const unsigned FULL = 0xffffffffu;

    // ---- load column j of G: top = D_j e_j, bottom = V[j][:] -------------
    const float Dj = g_D[(size_t)b * NY + j];
    const float4 v0 = *(const float4*)&g_V[(size_t)b * 256 + j * 8];
    const float4 v1 = *(const float4*)&g_V[(size_t)b * 256 + j * 8 + 4];

    float tf[32];
#pragma unroll
    for (int i = 0; i < 32; i++) tf[i] = (i == j) ? Dj : 0.f;
    float bt[8] = {v0.x, v0.y, v0.z, v0.w, v1.x, v1.y, v1.z, v1.w};

    // ---- Givens QR: zero the 8 bottom rows --------------------------------
#pragma unroll
    for (int jj = 0; jj < 32; jj++) {
#pragma unroll
        for (int k = 0; k < 8; k++) {
            float a, bb;
            { ull ab = __shfl_sync(FULL, pack2(tf[jj], bt[k]), jj);
              unpack2(ab, a, bb); }
            // pivot a = R[jj][jj] >= D_jj >= 1e-3 > 0 always
            float rinv = rsqrtf(fmaf(a, a, bb * bb));
            float c = a * rinv, s = bb * rinv;
            float t1 = fmaf(c, tf[jj], s * bt[k]);
            bt[k]  = fmaf(c, bt[k], -s * tf[jj]);
            tf[jj] = t1;
        }
    }

    // ---- stage R to smem (column j), compute column norm ------------------
    float nrm = 0.f;
#pragma unroll
    for (int i = 0; i < 32; i++) {
        Bsh[w][i][j] = tf[i];
        nrm = fmaf(tf[i], tf[i], nrm);
    }
    __syncwarp();

    // ---- pack into 16 f32x2 registers -------------------------------------
    ull gp[16];
#pragma unroll
    for (int i = 0; i < 16; i++) gp[i] = pack2(tf[2 * i], tf[2 * i + 1]);

    float e = 1.f;                              // column scale^2 (d^2)
    const float tol2 = 3e-10f;                  // (~1.7e-5)^2 relative

    // ---- one-sided Jacobi sweeps (XOR tournament: m = 1..31) -------------
    for (int sweep = 0; sweep < 10; sweep++) {
        int did = 0;
        for (int m = 1; m < 32; m++) {
            // fetch partner column ONCE (reused for dot + update)
            ull hp[16];
#pragma unroll
            for (int i = 0; i < 16; i++)
                hp[i] = __shfl_xor_sync(FULL, gp[i], m);
            float nrmo, eo;
            { ull neo = __shfl_xor_sync(FULL, pack2(nrm, e), m);
              unpack2(neo, nrmo, eo); }

            // dot: a_pq(stored), 4 accumulators, packed add-tree reduce
            ull a0 = 0ull, a1 = 0ull, a2v = 0ull, a3 = 0ull;
#pragma unroll
            for (int i = 0; i < 16; i += 4) {
                a0  = fma2_(gp[i],     hp[i],     a0);
                a1  = fma2_(gp[i + 1], hp[i + 1], a1);
                a2v = fma2_(gp[i + 2], hp[i + 2], a2v);
                a3  = fma2_(gp[i + 3], hp[i + 3], a3);
            }
            ull sred = add2_(add2_(a0, a1), add2_(a2v, a3));
            float slo, shi;
            unpack2(sred, slo, shi);
            float apq = slo + shi;

            // scale-invariant threshold
            bool rot = apq * apq > tol2 * nrm * nrmo;
            if (__any_sync(FULL, rot)) {
                did = 1;
                bool isp = j < (j ^ m);
                // tau = (aqq - app)_true / (2*apq_true); same on both lanes
                float dn = isp ? (eo * nrmo - e * nrm) : (e * nrm - eo * nrmo);
                float inv_sd = rsqrtf(e * eo);         // 1/sqrt(e*eo)  (validated)
                float tau = __fdividef(dn * (0.5f * inv_sd), apq);
                float t = __fdividef(copysignf(1.f, tau),
                                     fabsf(tau) + sqrtf(fmaf(tau, tau, 1.f)));
                if (!rot) t = 0.f;
                float rr = eo * inv_sd;                // sqrt(eo/e)
                float al = (isp ? -t : t) * rr;        // g += al * h
                ull a2p = pack2(al, al);
#pragma unroll
                for (int i = 0; i < 16; i++)
                    gp[i] = fma2_(a2p, hp[i], gp[i]);
                float ct2 = fmaf(t, t, 1.f);           // 1/c^2
                nrm = fmaf(al, apq, nrm) * ct2;        // stored-norm update
                e = __fdividef(e, ct2);                // d'^2 = c^2 d^2
            }
        }
        // ---- fold scale back into the column; exact norm recompute -------
        float d = sqrtf(e);
        ull d2 = pack2(d, d);
        ull na0 = 0ull, na1 = 0ull;
#pragma unroll
        for (int i = 0; i < 16; i += 2) {
            gp[i]     = mul2_(gp[i],     d2);
            gp[i + 1] = mul2_(gp[i + 1], d2);
            na0 = fma2_(gp[i],     gp[i],     na0);
            na1 = fma2_(gp[i + 1], gp[i + 1], na1);
        }
        float nlo, nhi, mlo, mhi;
        unpack2(na0, nlo, nhi); unpack2(na1, mlo, mhi);
        nrm = (nlo + mlo) + (nhi + mhi);
        e = 1.f;
        if (!did) break;
    }

    // ---- epilogue: eigenvalue + eigenvector recovery ---------------------
    float gf[32];
#pragma unroll
    for (int i = 0; i < 16; i++) unpack2(gp[i], gf[2 * i], gf[2 * i + 1]);

    const float s2 = nrm;                        // ||g'||^2 (exact from fold)
    const float fj = sqrtf(__fdividef(1.f, s2) + 1e-6f);  // sqrt(lam + EPS)

    // w = R^T g'  (g' register-resident; R upper-triangular: skip m > i)
    float accw[32];
#pragma unroll
    for (int i = 0; i < 32; i++) accw[i] = 0.f;
#pragma unroll
    for (int m = 0; m < 32; m++) {
        float gm = gf[m];                        // register, static index
#pragma unroll
        for (int i = m; i < 32; i++)             // R[m][i] == 0 exactly for i < m
            accw[i] = fmaf(Bsh[w][m][i], gm, accw[i]);   // broadcast loads
    }
    float nn = 0.f;
#pragma unroll
    for (int i = 0; i < 32; i++) nn = fmaf(accw[i], accw[i], nn);
    phsh[w][j] = __fdividef(fj, nn);             // phi = f / ||w||^2
    __syncwarp();

    // overwrite Bsh with W (unscaled eigvec columns)
#pragma unroll
    for (int i = 0; i < 32; i++) Bsh[w][i][j] = accw[i];
    __syncwarp();

    // ---- out = sum_k phi_k * w_k w_k^T  (row j per lane) -----------------
    float accO[32];
#pragma unroll
    for (int i = 0; i < 32; i++) accO[i] = 0.f;
    for (int k = 0; k < 32; k++) {
        float qjk = Bsh[w][j][k] * phsh[w][k];   // stride-33: conflict-free
#pragma unroll
        for (int i = 0; i < 32; i++)
            accO[i] = fmaf(Bsh[w][i][k], qjk, accO[i]);  // broadcast loads
    }
    __syncwarp();
#pragma unroll
    for (int i = 0; i < 32; i++) Bsh[w][j][i] = accO[i];  // stage row j
    __syncwarp();

    float* ob = out + (size_t)b * 1024;
#pragma unroll
    for (int t = 0; t < 8; t++) {                // coalesced 512B stores
        int idx = t * 128 + j * 4;
        int rr = idx >> 5, cc = idx & 31;
        float4 val = make_float4(Bsh[w][rr][cc], Bsh[w][rr][cc + 1],
                                 Bsh[w][rr][cc + 2], Bsh[w][rr][cc + 3]);
        *(float4*)&ob[idx] = val;
    }
}

// ---------------------------------------------------------------------------
extern "C" void kernel_launch(void* const* d_in, const int* in_sizes, int n_in,
                              void* d_out, int out_size) {
    const float* x  = (const float*)d_in[0];
    const float* W1 = (const float*)d_in[1];
    const float* b1 = (const float*)d_in[2];
    const float* WD = (const float*)d_in[3];
    const float* bD = (const float*)d_in[4];
    const float* WV = (const float*)d_in[5];
    const float* bV = (const float*)d_in[6];
    float* out = (float*)d_out;

    dim3 g1(NH / 64, NB / 64);
    feat_kernel<<<g1, 256>>>(x, W1, b1);

    dim3 g2(9, NB / 128);                        // bx=0: D head, bx=1..8: V
    heads_kernel<<<g2, 256>>>(WD, bD, WV, bV);

    jacobi_kernel<<<NB / 4, 128>>>(out);
}